// round 17
// baseline (speedup 1.0000x reference)
#include <cuda_runtime.h>
#include <cuda_fp16.h>
#include <cuda_pipeline.h>
#include <cstdint>

// Problem dims: B=32, L=512, D=256, H=4
#define BB 32
#define LL 512
#define DD 256
#define HH 4
#define NTOK (BB * LL)      // 16384
#define BH (BB * HH)        // 128
#define HD (HH * DD)        // 1024

// ---------------- device scratch (.bss, allocation-free) ----------------
__device__ __align__(256) float g_QpF[NTOK * DD];
__device__ __align__(256) __half g_QpH[NTOK * DD], g_KpH[NTOK * DD], g_VpH[NTOK * DD];
__device__ __align__(256) __half g_QhH[BH * LL * DD];     // (bh, l, d)
__device__ __align__(256) __half g_KhH[BH * LL * DD];     // (bh, l, d)
__device__ __align__(256) __half g_VtH[BH * DD * LL];     // (bh, d, l)
__device__ __align__(256) float g_Vsum[BH * DD];
__device__ __align__(256) __half g_VmH[NTOK * HD];        // (b, l, h*d)
__device__ __align__(256) float g_T1[NTOK * DD];
__device__ __align__(256) float g_XF[NTOK * DD];
__device__ __align__(256) __half g_XH[NTOK * DD];
__device__ __align__(256) __half g_YH[NTOK * DD];
__device__ __align__(256) float g_ZF[NTOK * DD];
// weights as B operand layout: [n][k] (k contiguous)
__device__ __align__(256) __half g_Wq[HD * DD], g_Wk[HD * DD], g_Wv[HD * DD];
__device__ __align__(256) __half g_Wo[DD * HD];
__device__ __align__(256) __half g_w1[DD * DD], g_w2[DD * DD];
__device__ int g_pad[NTOK];

// ---------------- mask decode, single launch, per-block dtype sniff ----------------
__global__ void decode_mask_kernel(const unsigned char* __restrict__ mb) {
    __shared__ int any;
    int tid = threadIdx.x;
    if (tid == 0) any = 0;
    __syncthreads();
    int i = blockIdx.x * 256 + tid;          // over NTOK/4 words
    if (mb[4 * i + 1]) atomicOr(&any, 1);
    __syncthreads();
    int base = blockIdx.x * 1024;
#pragma unroll
    for (int k = 0; k < 4; k++) {
        int t = base + k * 256 + tid;
        g_pad[t] = any ? (mb[t] != 0) : (((const int*)mb)[t] != 0);
    }
}

// ---------------- PE add for Q, K, V in one launch (grid.y selects) ----------------
__global__ void add_pe_all(const float4* __restrict__ Q, const float4* __restrict__ K,
                           const float4* __restrict__ V, const float* __restrict__ pe,
                           float4* __restrict__ QpF, __half2* __restrict__ QpH,
                           __half2* __restrict__ KpH, __half2* __restrict__ VpH) {
    int i = blockIdx.x * blockDim.x + threadIdx.x;   // over NTOK*DD/4
    if (i >= NTOK * DD / 4) return;
    int y = blockIdx.y;
    const float4* in = (y == 0) ? Q : (y == 1) ? K : V;
    __half2* outH = (y == 0) ? QpH : (y == 1) ? KpH : VpH;
    int d4 = i & 63;
    int l = (i >> 6) & (LL - 1);
    float4 v = in[i];
    float4 p = *(const float4*)(pe + l * DD + d4 * 4);
    v.x += p.x; v.y += p.y; v.z += p.z; v.w += p.w;
    if (y == 0) QpF[i] = v;
    outH[2 * i] = __floats2half2_rn(v.x, v.y);
    outH[2 * i + 1] = __floats2half2_rn(v.z, v.w);
}

// ---------------- all weight conversions, one launch (grid.y = 0..5) ----------------
__global__ void wconv_all(const float* __restrict__ Wq, const float* __restrict__ Wk,
                          const float* __restrict__ Wv, const float* __restrict__ Wo,
                          const float* __restrict__ w1, const float* __restrict__ w2,
                          __half* __restrict__ dWq, __half* __restrict__ dWk,
                          __half* __restrict__ dWv, __half* __restrict__ dWo,
                          __half2* __restrict__ dw1, __half2* __restrict__ dw2) {
    int y = blockIdx.y;
    if (y < 4) {
        __shared__ __half t[32][33];
        const float* src = (y == 0) ? Wq : (y == 1) ? Wk : (y == 2) ? Wv : Wo;
        __half* dst = (y == 0) ? dWq : (y == 1) ? dWk : (y == 2) ? dWv : dWo;
        int R = (y < 3) ? DD : HD;
        int C = (y < 3) ? HD : DD;
        int tilesC = C >> 5;
        if ((int)blockIdx.x >= (R >> 5) * tilesC) return;   // guard (exact at 256)
        int tr = (blockIdx.x / tilesC) << 5;
        int tc = (blockIdx.x % tilesC) << 5;
        int tx = threadIdx.x & 31, ty = threadIdx.x >> 5;
#pragma unroll
        for (int s = 0; s < 32; s += 8)
            t[ty + s][tx] = __float2half_rn(src[(size_t)(tr + ty + s) * C + tc + tx]);
        __syncthreads();
#pragma unroll
        for (int s = 0; s < 32; s += 8)
            dst[(size_t)(tc + ty + s) * R + tr + tx] = t[tx][ty + s];
    } else {
        int i = blockIdx.x * blockDim.x + threadIdx.x;
        if (i >= DD * DD / 4) return;
        const float4* s = (y == 4) ? (const float4*)w1 : (const float4*)w2;
        __half2* d = (y == 4) ? dw1 : dw2;
        float4 v = s[i];
        d[2 * i] = __floats2half2_rn(v.x, v.y);
        d[2 * i + 1] = __floats2half2_rn(v.z, v.w);
    }
}

// ---------------- Vsum[bh][d] = sum_l Vt[bh][d][l] (warp per row) ----------------
__global__ void vsum_kernel(const __half2* __restrict__ Vt, float* __restrict__ Vs) {
    int row = blockIdx.x * 8 + (threadIdx.x >> 5);   // over BH*DD = 32768 rows
    int lane = threadIdx.x & 31;
    const __half2* p = Vt + (size_t)row * (LL / 2);
    float s = 0.0f;
#pragma unroll
    for (int i = 0; i < 8; i++) {
        float2 v = __half22float2(p[i * 32 + lane]);
        s += v.x + v.y;
    }
#pragma unroll
    for (int off = 16; off > 0; off >>= 1) s += __shfl_xor_sync(0xFFFFFFFF, s, off);
    if (lane == 0) Vs[row] = s;
}

// ---------------- asm helpers ----------------
__device__ __forceinline__ uint32_t smem_u32(const void* p) {
    uint32_t a;
    asm("{ .reg .u64 t; cvta.to.shared.u64 t, %1; cvt.u32.u64 %0, t; }" : "=r"(a) : "l"(p));
    return a;
}
__device__ __forceinline__ void ldsm4(uint32_t& r0, uint32_t& r1, uint32_t& r2, uint32_t& r3,
                                      uint32_t addr) {
    asm volatile("ldmatrix.sync.aligned.m8n8.x4.shared.b16 {%0,%1,%2,%3}, [%4];"
                 : "=r"(r0), "=r"(r1), "=r"(r2), "=r"(r3) : "r"(addr));
}
__device__ __forceinline__ void mma16816(float* c, uint32_t a0, uint32_t a1, uint32_t a2,
                                         uint32_t a3, uint32_t b0, uint32_t b1) {
    asm volatile(
        "mma.sync.aligned.m16n8k16.row.col.f32.f16.f16.f32 "
        "{%0,%1,%2,%3}, {%4,%5,%6,%7}, {%8,%9}, {%0,%1,%2,%3};"
        : "+f"(c[0]), "+f"(c[1]), "+f"(c[2]), "+f"(c[3])
        : "r"(a0), "r"(a1), "r"(a2), "r"(a3), "r"(b0), "r"(b1));
}
__device__ __forceinline__ uint32_t packh2(float a, float b) {
    __half2 h = __floats2half2_rn(a, b);
    return *(uint32_t*)&h;
}

// ---------------- fp16 mma.sync GEMM, 3-stage cp.async pipeline ----------------
// CTA tile 128x128, 4 warps (128 threads), warp tile 64x64 (2M x 2N).
// Halves smem read traffic and LDSM count per MMA vs 32x64 warp tiles
// (A re-read by 2 warps, B by 2). Accumulation order per element unchanged.
#define MT 128
#define NT 128
#define KC 64
#define STG 32768          // A 16K + B 16K per stage
#define NSTG 3
#define GTHR 128

#define MODE_PLAIN 0
#define MODE_HEADSPLIT 1
#define MODE_VT 2

__global__ void __launch_bounds__(GTHR, 2)
gemm_h(const __half* __restrict__ A, const __half* __restrict__ B,
       float* __restrict__ outF, __half* __restrict__ outH, const float* __restrict__ bias,
       int K, long long aBatch, long long bBatch, long long cBatch, int ldc,
       int mode, float alpha, int doRelu,
       const __half* __restrict__ A2, const __half* __restrict__ B2,
       __half* __restrict__ outH2,
       const __half* __restrict__ A3, const __half* __restrict__ B3,
       __half* __restrict__ outH3) {
    extern __shared__ __align__(128) char smem[];

    const int bz = blockIdx.z;
    const int tid = threadIdx.x;
    const int wid = tid >> 5;
    const int l = tid & 31;
    const int wr = wid & 1;            // 2 warps in M
    const int wc = wid >> 1;           // 2 warps in N

    // triple-problem merge (projection launch):
    //   z=0: (A, B)  headsplit   z=1: (A2, B2) headsplit   z=2: (A3, B3) VT w/ swapped map
    const __half* Ab = A;
    const __half* Bb = B;
    __half* outHb = outH;
    int md = mode;
    int bm0, bn0;
    if (A2 && bz == 1) { Ab = A2; Bb = B2; outHb = outH2; }
    if (A3 && bz == 2) {
        Ab = A3; Bb = B3; outHb = outH3; md = MODE_VT;
        bm0 = blockIdx.x * MT;            // M over HD (8 tiles)
        bn0 = blockIdx.y * NT;            // N over NTOK (128 tiles)
    } else {
        bm0 = blockIdx.y * MT;
        bn0 = blockIdx.x * NT;
    }
    const bool batched = (A2 == nullptr) && (A3 == nullptr);
    const __half* gA = Ab + (batched ? bz * aBatch : 0) + (long long)bm0 * K;
    const __half* gB = Bb + (batched ? bz * bBatch : 0) + (long long)bn0 * K;
    const uint32_t sbase = smem_u32(smem);

    float c[4][8][4];
#pragma unroll
    for (int i = 0; i < 4; i++)
#pragma unroll
        for (int j = 0; j < 8; j++)
#pragma unroll
            for (int e = 0; e < 4; e++) c[i][j][e] = 0.0f;

    const int mrow = wr * 64 + ((l >> 3) & 1) * 8 + (l & 7);
    const int kpA = (l >> 4) & 1;
    const int nrow = wc * 64 + ((l >> 4) & 1) * 8 + (l & 7);
    const int kpB = (l >> 3) & 1;

    auto stage_fn = [&](int buf, int k0) {
        char* sA = smem + buf * STG;
        char* sB = sA + 16384;
#pragma unroll
        for (int it = 0; it < 8; it++) {   // A: 128 rows x 8 chunks(16B), 128 threads
            int idx = tid + it * GTHR;
            int r = idx >> 3, ch = idx & 7;
            __pipeline_memcpy_async(sA + r * 128 + ((ch ^ (r & 7)) << 4),
                                    gA + (long long)r * K + k0 + ch * 8, 16);
        }
#pragma unroll
        for (int it = 0; it < 8; it++) {
            int idx = tid + it * GTHR;
            int r = idx >> 3, ch = idx & 7;
            __pipeline_memcpy_async(sB + r * 128 + ((ch ^ (r & 7)) << 4),
                                    gB + (long long)r * K + k0 + ch * 8, 16);
        }
    };

    const int nt = K / KC;
    stage_fn(0, 0);
    __pipeline_commit();
    if (nt > 1) { stage_fn(1, KC); __pipeline_commit(); }

    for (int cc = 0; cc < nt; cc++) {
        if (cc < nt - 1) __pipeline_wait_prior(1);
        else __pipeline_wait_prior(0);
        __syncthreads();
        if (cc + 2 < nt) {
            stage_fn((cc + 2) % NSTG, (cc + 2) * KC);
            __pipeline_commit();
        }

        const int buf = cc % NSTG;
        const uint32_t sA = sbase + buf * STG;
        const uint32_t sB = sA + 16384;
#pragma unroll
        for (int ks = 0; ks < 4; ks++) {
            uint32_t a[4][4];
#pragma unroll
            for (int i = 0; i < 4; i++) {
                int row = mrow + i * 16;
                ldsm4(a[i][0], a[i][1], a[i][2], a[i][3],
                      sA + row * 128 + (((2 * ks + kpA) ^ (row & 7)) << 4));
            }
            uint32_t b[4][4];
#pragma unroll
            for (int g = 0; g < 4; g++) {
                int row = nrow + g * 16;
                ldsm4(b[g][0], b[g][1], b[g][2], b[g][3],
                      sB + row * 128 + (((2 * ks + kpB) ^ (row & 7)) << 4));
            }
#pragma unroll
            for (int i = 0; i < 4; i++)
#pragma unroll
                for (int j = 0; j < 8; j++) {
                    int g = j >> 1, h2 = (j & 1) << 1;
                    mma16816(c[i][j], a[i][0], a[i][1], a[i][2], a[i][3],
                             b[g][h2], b[g][h2 + 1]);
                }
        }
    }

    const int mb = bm0 + wr * 64 + (l >> 2);
    const int nb = bn0 + wc * 64 + (l & 3) * 2;
    auto emit2 = [&](int m, int n, float v0, float v1) {
        v0 *= alpha; v1 *= alpha;
        if (bias) { v0 += bias[n]; v1 += bias[n + 1]; }
        if (doRelu) { v0 = fmaxf(v0, 0.0f); v1 = fmaxf(v1, 0.0f); }
        size_t oidx;
        if (md == MODE_PLAIN) {
            oidx = (size_t)bz * cBatch + (size_t)m * ldc + n;
        } else if (md == MODE_HEADSPLIT) {
            int b_ = m >> 9, l_ = m & 511, h_ = n >> 8, d_ = n & 255;
            oidx = ((size_t)((b_ * HH + h_) * LL + l_)) * DD + d_;
        } else {  // MODE_VT: m over HD (h,d), n over NTOK (b,l) -> Vt[(b*H+h)*D+d][l]
            int h_ = m >> 8, d_ = m & 255, b_ = n >> 9, l_ = n & 511;
            oidx = ((size_t)((b_ * HH + h_) * DD + d_)) * LL + l_;
        }
        if (outF) *(float2*)(outF + oidx) = make_float2(v0, v1);
        else *(__half2*)(outHb + oidx) = __floats2half2_rn(v0, v1);
    };
#pragma unroll
    for (int i = 0; i < 4; i++) {
        int m = mb + i * 16;
#pragma unroll
        for (int j = 0; j < 8; j++) {
            int n = nb + j * 8;
            emit2(m, n, c[i][j][0], c[i][j][1]);
            emit2(m + 8, n, c[i][j][2], c[i][j][3]);
        }
    }
}

// ---------------- fused flash attention (LPT dispatch: heavy q-tiles first) ----------------
#define FSM_K 65536
#define FSM_V 131072
#define FSM_TOT 196608

__global__ void __launch_bounds__(256, 1)
flash_attn(const __half* __restrict__ Qh, const __half* __restrict__ Kh,
           const __half* __restrict__ Vt, const float* __restrict__ Vsum,
           __half* __restrict__ Om) {
    extern __shared__ __align__(128) char smem[];
    const int qt = (gridDim.y - 1) - blockIdx.y;   // y=0 -> qt=3 (most work) first
    const int bh = blockIdx.x;
    const int tid = threadIdx.x;
    const int w = tid >> 5;
    const int l = tid & 31;

    const __half* gQ = Qh + ((size_t)bh * LL + qt * 128) * DD;
    const __half* gK = Kh + (size_t)bh * LL * DD;
    const __half* gV = Vt + (size_t)bh * DD * LL;
    char* smQ = smem;
    char* smK = smem + FSM_K;
    char* smV = smem + FSM_V;
    const uint32_t sQ = smem_u32(smem);
    const uint32_t sK = sQ + FSM_K;
    const uint32_t sV = sQ + FSM_V;

#pragma unroll
    for (int cq = 0; cq < 4; cq++)
#pragma unroll
        for (int it = 0; it < 4; it++) {
            int idx = tid + it * 256;
            int r = idx >> 3, ch = idx & 7;
            __pipeline_memcpy_async(smQ + cq * 16384 + r * 128 + ((ch ^ (r & 7)) << 4),
                                    gQ + (size_t)r * DD + cq * 64 + ch * 8, 16);
        }
    __pipeline_commit();

    float o[32][4];
#pragma unroll
    for (int j = 0; j < 32; j++)
#pragma unroll
        for (int e = 0; e < 4; e++) o[j][e] = 0.0f;
    float mrun0 = -INFINITY, mrun1 = -INFINITY;
    float lrun0 = 0.0f, lrun1 = 0.0f;

    const int r0l = w * 16 + (l >> 2);
    const int r1l = r0l + 8;
    const int arow = w * 16 + ((l >> 3) & 1) * 8 + (l & 7);
    const int kpA = (l >> 4) & 1;
    const int brow = ((l >> 4) & 1) * 8 + (l & 7);
    const int kpB = (l >> 3) & 1;
    const float alpha = (float)(1.0 / (16.0 + 1e-6));

    for (int kt = 0; kt <= qt; kt++) {
#pragma unroll
        for (int ck = 0; ck < 4; ck++) {
#pragma unroll
            for (int it = 0; it < 4; it++) {
                int idx = tid + it * 256;
                int r = idx >> 3, ch = idx & 7;
                __pipeline_memcpy_async(smK + ck * 16384 + r * 128 + ((ch ^ (r & 7)) << 4),
                                        gK + (size_t)(kt * 128 + r) * DD + ck * 64 + ch * 8, 16);
            }
            __pipeline_commit();
        }
#pragma unroll
        for (int cv = 0; cv < 2; cv++) {
#pragma unroll
            for (int it = 0; it < 8; it++) {
                int idx = tid + it * 256;
                int r = idx >> 3, ch = idx & 7;
                __pipeline_memcpy_async(smV + cv * 32768 + r * 128 + ((ch ^ (r & 7)) << 4),
                                        gV + (size_t)r * LL + kt * 128 + cv * 64 + ch * 8, 16);
            }
            __pipeline_commit();
        }

        float c[16][4];
#pragma unroll
        for (int j = 0; j < 16; j++)
#pragma unroll
            for (int e = 0; e < 4; e++) c[j][e] = 0.0f;

#pragma unroll
        for (int ck = 0; ck < 4; ck++) {
            __pipeline_wait_prior(5 - ck);
            __syncthreads();
#pragma unroll
            for (int ks = 0; ks < 4; ks++) {
                uint32_t a0, a1, a2, a3;
                ldsm4(a0, a1, a2, a3,
                      sQ + ck * 16384 + arow * 128 + (((2 * ks + kpA) ^ (arow & 7)) << 4));
#pragma unroll
                for (int g = 0; g < 8; g++) {
                    int nr = g * 16 + brow;
                    uint32_t b0, b1, b2, b3;
                    ldsm4(b0, b1, b2, b3,
                          sK + ck * 16384 + nr * 128 + (((2 * ks + kpB) ^ (nr & 7)) << 4));
                    mma16816(c[2 * g], a0, a1, a2, a3, b0, b1);
                    mma16816(c[2 * g + 1], a0, a1, a2, a3, b2, b3);
                }
            }
        }

        if (kt == qt) {
#pragma unroll
            for (int j = 0; j < 16; j++) {
                int nb = j * 8 + (l & 3) * 2;
                c[j][0] = (nb     <= r0l) ? c[j][0] * alpha : -INFINITY;
                c[j][1] = (nb + 1 <= r0l) ? c[j][1] * alpha : -INFINITY;
                c[j][2] = (nb     <= r1l) ? c[j][2] * alpha : -INFINITY;
                c[j][3] = (nb + 1 <= r1l) ? c[j][3] * alpha : -INFINITY;
            }
        } else {
#pragma unroll
            for (int j = 0; j < 16; j++)
#pragma unroll
                for (int e = 0; e < 4; e++) c[j][e] *= alpha;
        }

        float mn0 = mrun0, mn1 = mrun1;
#pragma unroll
        for (int j = 0; j < 16; j++) {
            mn0 = fmaxf(mn0, fmaxf(c[j][0], c[j][1]));
            mn1 = fmaxf(mn1, fmaxf(c[j][2], c[j][3]));
        }
        mn0 = fmaxf(mn0, __shfl_xor_sync(0xFFFFFFFF, mn0, 1));
        mn0 = fmaxf(mn0, __shfl_xor_sync(0xFFFFFFFF, mn0, 2));
        mn1 = fmaxf(mn1, __shfl_xor_sync(0xFFFFFFFF, mn1, 1));
        mn1 = fmaxf(mn1, __shfl_xor_sync(0xFFFFFFFF, mn1, 2));
        float corr0 = __expf(mrun0 - mn0);
        float corr1 = __expf(mrun1 - mn1);
        mrun0 = mn0; mrun1 = mn1;

        float rs0 = 0.0f, rs1 = 0.0f;
        uint32_t pk[16][2];
#pragma unroll
        for (int j = 0; j < 16; j++) {
            float p0 = __expf(c[j][0] - mn0);
            float p1 = __expf(c[j][1] - mn0);
            float p2 = __expf(c[j][2] - mn1);
            float p3 = __expf(c[j][3] - mn1);
            rs0 += p0 + p1; rs1 += p2 + p3;
            pk[j][0] = packh2(p0, p1);
            pk[j][1] = packh2(p2, p3);
        }
        rs0 += __shfl_xor_sync(0xFFFFFFFF, rs0, 1);
        rs0 += __shfl_xor_sync(0xFFFFFFFF, rs0, 2);
        rs1 += __shfl_xor_sync(0xFFFFFFFF, rs1, 1);
        rs1 += __shfl_xor_sync(0xFFFFFFFF, rs1, 2);
        lrun0 = lrun0 * corr0 + rs0;
        lrun1 = lrun1 * corr1 + rs1;
#pragma unroll
        for (int j = 0; j < 32; j++) {
            o[j][0] *= corr0; o[j][1] *= corr0;
            o[j][2] *= corr1; o[j][3] *= corr1;
        }

#pragma unroll
        for (int hv = 0; hv < 2; hv++) {
            __pipeline_wait_prior(1 - hv);
            __syncthreads();
#pragma unroll
            for (int k2 = 0; k2 < 4; k2++) {
                int kk = hv * 4 + k2;
                uint32_t a0 = pk[2 * kk][0], a1 = pk[2 * kk][1];
                uint32_t a2 = pk[2 * kk + 1][0], a3 = pk[2 * kk + 1][1];
#pragma unroll
                for (int g = 0; g < 16; g++) {
                    int nr = g * 16 + brow;
                    uint32_t b0, b1, b2, b3;
                    ldsm4(b0, b1, b2, b3,
                          sV + hv * 32768 + nr * 128 + (((2 * k2 + kpB) ^ (nr & 7)) << 4));
                    mma16816(o[2 * g], a0, a1, a2, a3, b0, b1);
                    mma16816(o[2 * g + 1], a0, a1, a2, a3, b2, b3);
                }
            }
        }
        __syncthreads();
    }

    float inv0 = 1.0f / lrun0, inv1 = 1.0f / lrun1;
    int q0 = qt * 128 + r0l, q1 = q0 + 8;
    int b_ = bh >> 2, h_ = bh & 3;
    int pad0 = g_pad[(b_ << 9) + q0];
    int pad1 = g_pad[(b_ << 9) + q1];
    const float i512 = 1.0f / 512.0f;
    const float* vs = Vsum + bh * DD;
    size_t base0 = (size_t)(b_ * 512 + q0) * HD + h_ * DD;
    size_t base1 = (size_t)(b_ * 512 + q1) * HD + h_ * DD;
#pragma unroll
    for (int j = 0; j < 32; j++) {
        int d = j * 8 + (l & 3) * 2;
        float v0 = o[j][0] * inv0, v1 = o[j][1] * inv0;
        float v2 = o[j][2] * inv1, v3 = o[j][3] * inv1;
        if (pad0) { v0 = vs[d] * i512; v1 = vs[d + 1] * i512; }
        if (pad1) { v2 = vs[d] * i512; v3 = vs[d + 1] * i512; }
        *(__half2*)(Om + base0 + d) = __floats2half2_rn(v0, v1);
        *(__half2*)(Om + base1 + d) = __floats2half2_rn(v2, v3);
    }
}

// ---------------- residual + layernorm: warp per row, zero barriers ----------------
__global__ void __launch_bounds__(256)
ln_residual_kernel(const float* __restrict__ Ain, const float* __restrict__ Bin,
                   const float* __restrict__ gamma, const float* __restrict__ beta,
                   float* __restrict__ outF, __half* __restrict__ outH) {
    int row = blockIdx.x * 8 + (threadIdx.x >> 5);
    int l = threadIdx.x & 31;
    size_t base = (size_t)row * DD + l * 8;

    float4 a0 = *(const float4*)(Ain + base);
    float4 a1 = *(const float4*)(Ain + base + 4);
    float4 b0 = *(const float4*)(Bin + base);
    float4 b1 = *(const float4*)(Bin + base + 4);
    float x[8] = {a0.x + b0.x, a0.y + b0.y, a0.z + b0.z, a0.w + b0.w,
                  a1.x + b1.x, a1.y + b1.y, a1.z + b1.z, a1.w + b1.w};

    float s = 0.0f;
#pragma unroll
    for (int e = 0; e < 8; e++) s += x[e];
#pragma unroll
    for (int off = 16; off > 0; off >>= 1) s += __shfl_xor_sync(0xFFFFFFFF, s, off);
    float mu = s * (1.0f / DD);

    float sq = 0.0f;
#pragma unroll
    for (int e = 0; e < 8; e++) { float d = x[e] - mu; sq += d * d; }
#pragma unroll
    for (int off = 16; off > 0; off >>= 1) sq += __shfl_xor_sync(0xFFFFFFFF, sq, off);
    float rstd = rsqrtf(sq * (1.0f / DD) + 1e-5f);

    float4 g0 = *(const float4*)(gamma + l * 8);
    float4 g1 = *(const float4*)(gamma + l * 8 + 4);
    float4 be0 = *(const float4*)(beta + l * 8);
    float4 be1 = *(const float4*)(beta + l * 8 + 4);
    float y[8];
    y[0] = (x[0] - mu) * rstd * g0.x + be0.x;
    y[1] = (x[1] - mu) * rstd * g0.y + be0.y;
    y[2] = (x[2] - mu) * rstd * g0.z + be0.z;
    y[3] = (x[3] - mu) * rstd * g0.w + be0.w;
    y[4] = (x[4] - mu) * rstd * g1.x + be1.x;
    y[5] = (x[5] - mu) * rstd * g1.y + be1.y;
    y[6] = (x[6] - mu) * rstd * g1.z + be1.z;
    y[7] = (x[7] - mu) * rstd * g1.w + be1.w;

    if (outF) {
        *(float4*)(outF + base) = make_float4(y[0], y[1], y[2], y[3]);
        *(float4*)(outF + base + 4) = make_float4(y[4], y[5], y[6], y[7]);
    }
    if (outH) {
        __half2 h[4] = {__floats2half2_rn(y[0], y[1]), __floats2half2_rn(y[2], y[3]),
                        __floats2half2_rn(y[4], y[5]), __floats2half2_rn(y[6], y[7])};
        *(float4*)(outH + base) = *(float4*)h;
    }
}

// ---------------- host orchestration ----------------
#define SYM(p, s) void* p; cudaGetSymbolAddress(&p, s)

extern "C" void kernel_launch(void* const* d_in, const int* in_sizes, int n_in,
                              void* d_out, int out_size) {
    (void)in_sizes; (void)n_in; (void)out_size;
    const float* Q    = (const float*)d_in[0];
    const float* K    = (const float*)d_in[1];
    const float* V    = (const float*)d_in[2];
    const void*  mask = d_in[3];
    const float* pe   = (const float*)d_in[4];
    const float* W_q  = (const float*)d_in[5];
    const float* W_k  = (const float*)d_in[6];
    const float* W_v  = (const float*)d_in[7];
    const float* W_o  = (const float*)d_in[8];
    const float* w1   = (const float*)d_in[9];
    const float* b1   = (const float*)d_in[10];
    const float* w2   = (const float*)d_in[11];
    const float* b2   = (const float*)d_in[12];
    const float* gamma = (const float*)d_in[13];
    const float* beta  = (const float*)d_in[14];
    float* out = (float*)d_out;

    SYM(pQpF, g_QpF);
    SYM(pQpH, g_QpH); SYM(pKpH, g_KpH); SYM(pVpH, g_VpH);
    SYM(pQhH, g_QhH); SYM(pKhH, g_KhH); SYM(pVtH, g_VtH);
    SYM(pVsum, g_Vsum); SYM(pVmH, g_VmH);
    SYM(pT1, g_T1); SYM(pXF, g_XF); SYM(pXH, g_XH); SYM(pYH, g_YH); SYM(pZF, g_ZF);
    SYM(pWq, g_Wq); SYM(pWk, g_Wk); SYM(pWv, g_Wv); SYM(pWo, g_Wo);
    SYM(pw1, g_w1); SYM(pw2, g_w2);

    cudaFuncSetAttribute(gemm_h, cudaFuncAttributeMaxDynamicSharedMemorySize, NSTG * STG);
    cudaFuncSetAttribute(flash_attn, cudaFuncAttributeMaxDynamicSharedMemorySize, FSM_TOT);

    typedef __half hf;

    // 1) mask decode (single launch, per-block dtype sniff)
    decode_mask_kernel<<<NTOK / 1024, 256>>>((const unsigned char*)mask);

    // 2) PE add + fp16 convert (Q, K, V in one launch)
    {
        int q4 = NTOK * DD / 4, qb = (q4 + 255) / 256;
        add_pe_all<<<dim3(qb, 3), 256>>>((const float4*)Q, (const float4*)K,
                                         (const float4*)V, pe, (float4*)pQpF,
                                         (__half2*)pQpH, (__half2*)pKpH, (__half2*)pVpH);
    }

    // 3) all weight conversions in one launch
    wconv_all<<<dim3(256, 6), 256>>>(W_q, W_k, W_v, W_o, w1, w2,
                                     (hf*)pWq, (hf*)pWk, (hf*)pWv, (hf*)pWo,
                                     (__half2*)pw1, (__half2*)pw2);

    // 4) ALL THREE projections in one launch:
    //    z=0: Qp@Wq -> Qh (headsplit), z=1: Kp@Wk -> Kh (headsplit),
    //    z=2: Wv@Vp -> Vt (swapped block map, transposed scatter)
    {
        dim3 g(HD / NT, NTOK / MT, 3);
        gemm_h<<<g, GTHR, NSTG * STG>>>((hf*)pQpH, (hf*)pWq, nullptr, (hf*)pQhH, nullptr,
                                        DD, 0, 0, 0, 0, MODE_HEADSPLIT, 1.0f, 0,
                                        (hf*)pKpH, (hf*)pWk, (hf*)pKhH,
                                        (hf*)pWv, (hf*)pVpH, (hf*)pVtH);
    }

    // 5) Vsum from Vt (warp per row)
    vsum_kernel<<<BH * DD / 8, 256>>>((const __half2*)pVtH, (float*)pVsum);

    // 6) fused flash attention -> merged (b, l, h*d); LPT: heavy q-tiles dispatch first
    {
        dim3 g(BH, LL / 128);
        flash_attn<<<g, 256, FSM_TOT>>>((hf*)pQhH, (hf*)pKhH, (hf*)pVtH,
                                        (float*)pVsum, (hf*)pVmH);
    }

    // 7) output projection: T1 = Vm @ W_o  (M=16384, N=256, K=1024)
    {
        dim3 g(DD / NT, NTOK / MT, 1);
        gemm_h<<<g, GTHR, NSTG * STG>>>((hf*)pVmH, (hf*)pWo, (float*)pT1, nullptr, nullptr,
                                        HD, 0, 0, 0, DD, MODE_PLAIN, 1.0f, 0,
                                        nullptr, nullptr, nullptr, nullptr, nullptr, nullptr);
    }

    // 8) X = LN(Qp + T1)
    ln_residual_kernel<<<NTOK / 8, 256>>>((float*)pQpF, (float*)pT1, gamma, beta,
                                          (float*)pXF, (hf*)pXH);

    // 9) FFN: Y = relu(X @ w1^T + b1); Z = Y @ w2^T + b2
    {
        dim3 g(DD / NT, NTOK / MT, 1);
        gemm_h<<<g, GTHR, NSTG * STG>>>((hf*)pXH, (hf*)pw1, nullptr, (hf*)pYH, b1,
                                        DD, 0, 0, 0, DD, MODE_PLAIN, 1.0f, 1,
                                        nullptr, nullptr, nullptr, nullptr, nullptr, nullptr);
        gemm_h<<<g, GTHR, NSTG * STG>>>((hf*)pYH, (hf*)pw2, (float*)pZF, nullptr, b2,
                                        DD, 0, 0, 0, DD, MODE_PLAIN, 1.0f, 0,
                                        nullptr, nullptr, nullptr, nullptr, nullptr, nullptr);
    }

    // 10) out = LN(Z + X)
    ln_residual_kernel<<<NTOK / 8, 256>>>((float*)pZF, (float*)pXF, gamma, beta, out, nullptr);
}